// round 13
// baseline (speedup 1.0000x reference)
#include <cuda_runtime.h>
#include <cuda_fp16.h>
#include <cstdint>

// GlobalAggregator fused v7: B=128,N=512,K=12,DIM=128.
// CTA = 192 thr (6 warps) = 16 bn = 192 rows = 12 m16 tiles (2/warp).
// Both tiles' A resident -> each b-frag load feeds 2 HMMAs (b traffic halved).
// 3 CTAs/SM (regs ~112); cat aliases dead feat smem.

#define KK 12
#define DIMD 128
#define BN_TOTAL (128 * 512)
#define TILE_BN 16
#define TILE_R 192
#define GRID_F (BN_TOTAL / TILE_BN)   // 4096
#define FSTR 68                        // feat row stride in u32 (136 fp16)
#define NWARP 6

__device__ uint2 g_bfrag1[128 * 32];   // w1 frags, [(nt*8+kt)*32+lane]
__device__ uint2 g_bfrag3[256 * 32];   // w3 frags, [(kt*16+nt)*32+lane]
__device__ float4 g_w1w2[64];          // (w1last pair, w2 pair) per (nt, tg)

// ---- helpers ----
__device__ __forceinline__ uint32_t packh(float lo, float hi) {
    uint32_t r;
    asm("cvt.rn.f16x2.f32 %0, %1, %2;" : "=r"(r) : "f"(hi), "f"(lo));
    return r;
}
__device__ __forceinline__ void mma16816h(float c[4],
                                          uint32_t a0, uint32_t a1, uint32_t a2, uint32_t a3,
                                          uint32_t b0, uint32_t b1) {
    asm volatile("mma.sync.aligned.m16n8k16.row.col.f32.f16.f16.f32 "
                 "{%0,%1,%2,%3},{%4,%5,%6,%7},{%8,%9},{%0,%1,%2,%3};"
                 : "+f"(c[0]), "+f"(c[1]), "+f"(c[2]), "+f"(c[3])
                 : "r"(a0), "r"(a1), "r"(a2), "r"(a3), "r"(b0), "r"(b1));
}
__device__ __forceinline__ void ldsm4(uint32_t r[4], uint32_t saddr) {
    asm volatile("ldmatrix.sync.aligned.m8n8.x4.shared.b16 {%0,%1,%2,%3}, [%4];"
                 : "=r"(r[0]), "=r"(r[1]), "=r"(r[2]), "=r"(r[3]) : "r"(saddr));
}
__device__ __forceinline__ uint32_t smem_u32(const void* p) {
    uint32_t a;
    asm("{ .reg .u64 t; cvta.to.shared.u64 t, %1; cvt.u32.u64 %0, t; }" : "=r"(a) : "l"(p));
    return a;
}
__device__ __forceinline__ float lrelu(float x) {
    return fmaxf(x, 0.f) + 0.2f * fminf(x, 0.f);
}

// ---------------- prep: bake B fragments ----------------
__global__ void prep_kernel(const float* __restrict__ w1,
                            const float* __restrict__ w2,
                            const float* __restrict__ w3) {
    int idx = blockIdx.x * 256 + threadIdx.x;
    if (idx < 4096) {                       // w1 frags, [nt][kt] order
        int gi = idx >> 5, lane = idx & 31;
        int nt = gi >> 3, kt = gi & 7;
        int g = lane >> 2, tg = lane & 3;
        int n = nt * 8 + g, k0 = kt * 16 + tg * 2;
        float v0 = w1[k0 * DIMD + n],       v1 = w1[(k0 + 1) * DIMD + n];
        float v2 = w1[(k0 + 8) * DIMD + n], v3 = w1[(k0 + 9) * DIMD + n];
        g_bfrag1[idx] = make_uint2(packh(v0, v1), packh(v2, v3));
    } else if (idx < 4096 + 8192) {         // w3 frags, [kt][nt] order (K=256)
        int j = idx - 4096;
        int gi = j >> 5, lane = j & 31;
        int kt = gi >> 4, nt = gi & 15;
        int g = lane >> 2, tg = lane & 3;
        int n = nt * 8 + g, k0 = kt * 16 + tg * 2;
        float v0 = w3[k0 * DIMD + n],       v1 = w3[(k0 + 1) * DIMD + n];
        float v2 = w3[(k0 + 8) * DIMD + n], v3 = w3[(k0 + 9) * DIMD + n];
        g_bfrag3[j] = make_uint2(packh(v0, v1), packh(v2, v3));
    } else if (idx < 4096 + 8192 + 64) {
        int t = idx - 4096 - 8192;
        int nt = t >> 2, tq = t & 3;
        int c0 = nt * 8 + tq * 2;
        g_w1w2[t] = make_float4(w1[128 * DIMD + c0], w1[128 * DIMD + c0 + 1],
                                w2[c0], w2[c0 + 1]);
    }
}

// ---------------- fused kernel ----------------
// dyn smem: feat 192*68 u32 (cat_h aliases feat after gemm1) | scores 192 f32
#define SM_SCORES (TILE_R * FSTR)
#define SM_BYTES  ((TILE_R * FSTR + TILE_R) * 4)   // 52992

__global__ __launch_bounds__(192, 3) void fused_kernel(
    const float* __restrict__ self_v,   // [BN,128]
    const float* __restrict__ neigh,    // [BN,12,128]
    const float* __restrict__ nw,       // [BN,12]
    const float* __restrict__ extra,    // [BN,128]
    float* __restrict__ out)            // [BN,128]
{
    extern __shared__ uint32_t sm[];
    uint32_t* feat = sm;
    float* scores_s = (float*)(sm + SM_SCORES);
    uint32_t* cat_h = sm;               // aliases feat (dead after gemm1)

    const int tid = threadIdx.x, wid = tid >> 5, lane = tid & 31;
    const int g = lane >> 2, tg = lane & 3;
    const int bn0 = blockIdx.x * TILE_BN;
    const unsigned row0 = blockIdx.x * TILE_R;

    // ---- stage feat = neigh * extra (fp16) into smem (default policy: L2 keeps it)
    {
        const float4* ng4 = (const float4*)neigh;
        const float4* ex4 = (const float4*)extra;
#pragma unroll
        for (int r = wid; r < TILE_R; r += NWARP) {
            unsigned gr = row0 + r;
            unsigned bnr = bn0 + r / KK;
            float4 nv = ng4[(size_t)gr * 32 + lane];
            float4 ev = __ldg(ex4 + (size_t)bnr * 32 + lane);
            feat[r * FSTR + 2 * lane]     = packh(nv.x * ev.x, nv.y * ev.y);
            feat[r * FSTR + 2 * lane + 1] = packh(nv.z * ev.z, nv.w * ev.w);
        }
    }
    __syncthreads();

    // ---- gemm1: warp owns 2 m16 tiles, BOTH A tiles resident; one b load
    //      feeds both tiles (b traffic halved). nt unrolled x2 -> 4 MMA chains.
    uint32_t A0[8][4], A1[8][4];
    {
        const uint32_t fb = smem_u32(feat);
        uint32_t r0 = (uint32_t)(32 * wid + (lane & 15));
        uint32_t co = (uint32_t)((lane >> 4) * 4);
#pragma unroll
        for (int kt = 0; kt < 8; kt++) {
            ldsm4(A0[kt], fb + (r0 * FSTR + kt * 8 + co) * 4);
            ldsm4(A1[kt], fb + ((r0 + 16) * FSTR + kt * 8 + co) * 4);
        }
    }
    const unsigned gr = row0 + 32 * wid + g;
    const float nwa0 = __ldg(nw + gr);        // tile0 row g
    const float nwa1 = __ldg(nw + gr + 8);    // tile0 row g+8
    const float nwb0 = __ldg(nw + gr + 16);   // tile1 row g
    const float nwb1 = __ldg(nw + gr + 24);   // tile1 row g+8
    float rsA0 = 0.f, rsA1 = 0.f, rsB0 = 0.f, rsB1 = 0.f;

#pragma unroll
    for (int nt0 = 0; nt0 < 16; nt0 += 2) {
        float acc[2][2][4];   // [tile][u][quad]
#pragma unroll
        for (int t = 0; t < 2; t++)
#pragma unroll
            for (int u = 0; u < 2; u++)
#pragma unroll
                for (int q = 0; q < 4; q++) acc[t][u][q] = 0.f;
#pragma unroll
        for (int kt = 0; kt < 8; kt++) {
#pragma unroll
            for (int u = 0; u < 2; u++) {
                uint2 b = __ldg(&g_bfrag1[((nt0 + u) * 8 + kt) * 32 + lane]);
                mma16816h(acc[0][u], A0[kt][0], A0[kt][1], A0[kt][2], A0[kt][3], b.x, b.y);
                mma16816h(acc[1][u], A1[kt][0], A1[kt][1], A1[kt][2], A1[kt][3], b.x, b.y);
            }
        }
#pragma unroll
        for (int u = 0; u < 2; u++) {
            float4 ww = g_w1w2[(nt0 + u) * 4 + tg];
            float v0 = lrelu(acc[0][u][0] + nwa0 * ww.x);
            float v1 = lrelu(acc[0][u][1] + nwa0 * ww.y);
            float v2 = lrelu(acc[0][u][2] + nwa1 * ww.x);
            float v3 = lrelu(acc[0][u][3] + nwa1 * ww.y);
            rsA0 = fmaf(v0, ww.z, fmaf(v1, ww.w, rsA0));
            rsA1 = fmaf(v2, ww.z, fmaf(v3, ww.w, rsA1));
            v0 = lrelu(acc[1][u][0] + nwb0 * ww.x);
            v1 = lrelu(acc[1][u][1] + nwb0 * ww.y);
            v2 = lrelu(acc[1][u][2] + nwb1 * ww.x);
            v3 = lrelu(acc[1][u][3] + nwb1 * ww.y);
            rsB0 = fmaf(v0, ww.z, fmaf(v1, ww.w, rsB0));
            rsB1 = fmaf(v2, ww.z, fmaf(v3, ww.w, rsB1));
        }
    }
    rsA0 += __shfl_xor_sync(0xffffffffu, rsA0, 1);
    rsA0 += __shfl_xor_sync(0xffffffffu, rsA0, 2);
    rsA1 += __shfl_xor_sync(0xffffffffu, rsA1, 1);
    rsA1 += __shfl_xor_sync(0xffffffffu, rsA1, 2);
    rsB0 += __shfl_xor_sync(0xffffffffu, rsB0, 1);
    rsB0 += __shfl_xor_sync(0xffffffffu, rsB0, 2);
    rsB1 += __shfl_xor_sync(0xffffffffu, rsB1, 1);
    rsB1 += __shfl_xor_sync(0xffffffffu, rsB1, 2);
    if (tg == 0) {
        scores_s[32 * wid + g]      = rsA0;
        scores_s[32 * wid + g + 8]  = rsA1;
        scores_s[32 * wid + g + 16] = rsB0;
        scores_s[32 * wid + g + 24] = rsB1;
    }
    __syncthreads();   // gemm1 feat reads complete -> cat may overwrite feat

    // ---- softmax + agg + cat: 16 bn over 6 warps (agg reload = L2 hit)
    for (int bnl = wid; bnl < TILE_BN; bnl += NWARP) {
        const unsigned gbn = bn0 + bnl;
        float alpha[KK];
        {
            float s[KK];
#pragma unroll
            for (int k = 0; k < KK; k++) s[k] = scores_s[bnl * KK + k];
            float mx = s[0];
#pragma unroll
            for (int k = 1; k < KK; k++) mx = fmaxf(mx, s[k]);
            float tot = 0.f;
#pragma unroll
            for (int k = 0; k < KK; k++) { alpha[k] = __expf(s[k] - mx); tot += alpha[k]; }
            float inv = 1.f / tot;
#pragma unroll
            for (int k = 0; k < KK; k++) alpha[k] *= inv;
        }
        const float4* nb4 = (const float4*)neigh + (size_t)gbn * KK * 32;
        float4 agg = make_float4(0.f, 0.f, 0.f, 0.f);
#pragma unroll
        for (int k = 0; k < KK; k++) {
            float4 v = nb4[k * 32 + lane];
            agg.x = fmaf(alpha[k], v.x, agg.x);
            agg.y = fmaf(alpha[k], v.y, agg.y);
            agg.z = fmaf(alpha[k], v.z, agg.z);
            agg.w = fmaf(alpha[k], v.w, agg.w);
        }
        float4 sv = *((const float4*)self_v + (size_t)gbn * 32 + lane);
        cat_h[bnl * 132 + 2 * lane]          = packh(sv.x, sv.y);
        cat_h[bnl * 132 + 2 * lane + 1]      = packh(sv.z, sv.w);
        cat_h[bnl * 132 + 64 + 2 * lane]     = packh(agg.x, agg.y);
        cat_h[bnl * 132 + 64 + 2 * lane + 1] = packh(agg.z, agg.w);
    }
    __syncthreads();

    // ---- w3 GEMM: one full m16 tile (16 bn), 16 nt over 6 warps
    for (int nt = wid; nt < 16; nt += NWARP) {
        float acc3[4] = {0.f, 0.f, 0.f, 0.f};
#pragma unroll
        for (int kt = 0; kt < 16; kt++) {
            uint32_t a0 = cat_h[g * 132 + kt * 8 + tg];
            uint32_t a1 = cat_h[(g + 8) * 132 + kt * 8 + tg];
            uint32_t a2 = cat_h[g * 132 + kt * 8 + tg + 4];
            uint32_t a3 = cat_h[(g + 8) * 132 + kt * 8 + tg + 4];
            uint2 bq = __ldg(&g_bfrag3[(kt * 16 + nt) * 32 + lane]);
            mma16816h(acc3, a0, a1, a2, a3, bq.x, bq.y);
        }
        float2 o0 = make_float2(fmaxf(acc3[0], 0.f), fmaxf(acc3[1], 0.f));
        float2 o1 = make_float2(fmaxf(acc3[2], 0.f), fmaxf(acc3[3], 0.f));
        *(float2*)(out + (size_t)(bn0 + g) * DIMD + nt * 8 + 2 * tg) = o0;
        *(float2*)(out + (size_t)(bn0 + g + 8) * DIMD + nt * 8 + 2 * tg) = o1;
    }
}

// ---------------- launch ----------------
extern "C" void kernel_launch(void* const* d_in, const int* in_sizes, int n_in,
                              void* d_out, int out_size) {
    const float* self_v = (const float*)d_in[0];
    const float* neigh  = (const float*)d_in[1];
    const float* nw     = (const float*)d_in[2];
    const float* extra  = (const float*)d_in[3];
    const float* w1     = (const float*)d_in[6];
    const float* w2     = (const float*)d_in[7];
    const float* w3     = (const float*)d_in[8];
    float* out = (float*)d_out;

    static bool attr_set = false;
    if (!attr_set) {
        cudaFuncSetAttribute(fused_kernel, cudaFuncAttributeMaxDynamicSharedMemorySize, SM_BYTES);
        attr_set = true;
    }

    prep_kernel<<<49, 256>>>(w1, w2, w3);
    fused_kernel<<<GRID_F, 192, SM_BYTES>>>(self_v, neigh, nw, extra, out);
}

// round 14
// speedup vs baseline: 1.3378x; 1.3378x over previous
#include <cuda_runtime.h>
#include <cuda_fp16.h>
#include <cstdint>

// GlobalAggregator fused v8: B=128,N=512,K=12,DIM=128.
// Round-10 gemm1 shape (1 A-tile resident, nt x4 unroll, 3 CTAs/SM) +
// warp-local staging (each warp stages its own 32 rows -> __syncwarp only).

#define KK 12
#define DIMD 128
#define BN_TOTAL (128 * 512)
#define TILE_BN 16
#define TILE_R 192
#define GRID_F (BN_TOTAL / TILE_BN)   // 4096
#define FSTR 68                        // feat row stride in u32 (136 fp16)
#define NWARP 6

__device__ uint2 g_bfrag1[128 * 32];   // w1 frags, [(nt*8+kt)*32+lane]
__device__ uint2 g_bfrag3[256 * 32];   // w3 frags, [(kt*16+nt)*32+lane]
__device__ float4 g_w1w2[64];          // (w1last pair, w2 pair) per (nt, tg)

// ---- helpers ----
__device__ __forceinline__ uint32_t packh(float lo, float hi) {
    uint32_t r;
    asm("cvt.rn.f16x2.f32 %0, %1, %2;" : "=r"(r) : "f"(hi), "f"(lo));
    return r;
}
__device__ __forceinline__ void mma16816h(float c[4],
                                          uint32_t a0, uint32_t a1, uint32_t a2, uint32_t a3,
                                          uint32_t b0, uint32_t b1) {
    asm volatile("mma.sync.aligned.m16n8k16.row.col.f32.f16.f16.f32 "
                 "{%0,%1,%2,%3},{%4,%5,%6,%7},{%8,%9},{%0,%1,%2,%3};"
                 : "+f"(c[0]), "+f"(c[1]), "+f"(c[2]), "+f"(c[3])
                 : "r"(a0), "r"(a1), "r"(a2), "r"(a3), "r"(b0), "r"(b1));
}
__device__ __forceinline__ void ldsm4(uint32_t r[4], uint32_t saddr) {
    asm volatile("ldmatrix.sync.aligned.m8n8.x4.shared.b16 {%0,%1,%2,%3}, [%4];"
                 : "=r"(r[0]), "=r"(r[1]), "=r"(r[2]), "=r"(r[3]) : "r"(saddr));
}
__device__ __forceinline__ uint32_t smem_u32(const void* p) {
    uint32_t a;
    asm("{ .reg .u64 t; cvta.to.shared.u64 t, %1; cvt.u32.u64 %0, t; }" : "=r"(a) : "l"(p));
    return a;
}
__device__ __forceinline__ float lrelu(float x) {
    return fmaxf(x, 0.f) + 0.2f * fminf(x, 0.f);
}

// ---------------- prep: bake B fragments ----------------
__global__ void prep_kernel(const float* __restrict__ w1,
                            const float* __restrict__ w2,
                            const float* __restrict__ w3) {
    int idx = blockIdx.x * 256 + threadIdx.x;
    if (idx < 4096) {                       // w1 frags, [nt][kt] order
        int gi = idx >> 5, lane = idx & 31;
        int nt = gi >> 3, kt = gi & 7;
        int g = lane >> 2, tg = lane & 3;
        int n = nt * 8 + g, k0 = kt * 16 + tg * 2;
        float v0 = w1[k0 * DIMD + n],       v1 = w1[(k0 + 1) * DIMD + n];
        float v2 = w1[(k0 + 8) * DIMD + n], v3 = w1[(k0 + 9) * DIMD + n];
        g_bfrag1[idx] = make_uint2(packh(v0, v1), packh(v2, v3));
    } else if (idx < 4096 + 8192) {         // w3 frags, [kt][nt] order (K=256)
        int j = idx - 4096;
        int gi = j >> 5, lane = j & 31;
        int kt = gi >> 4, nt = gi & 15;
        int g = lane >> 2, tg = lane & 3;
        int n = nt * 8 + g, k0 = kt * 16 + tg * 2;
        float v0 = w3[k0 * DIMD + n],       v1 = w3[(k0 + 1) * DIMD + n];
        float v2 = w3[(k0 + 8) * DIMD + n], v3 = w3[(k0 + 9) * DIMD + n];
        g_bfrag3[j] = make_uint2(packh(v0, v1), packh(v2, v3));
    } else if (idx < 4096 + 8192 + 64) {
        int t = idx - 4096 - 8192;
        int nt = t >> 2, tq = t & 3;
        int c0 = nt * 8 + tq * 2;
        g_w1w2[t] = make_float4(w1[128 * DIMD + c0], w1[128 * DIMD + c0 + 1],
                                w2[c0], w2[c0 + 1]);
    }
}

// ---------------- fused kernel ----------------
// dyn smem: feat 192*68 u32 (cat_h aliases feat after gemm1) | scores 192 f32
#define SM_SCORES (TILE_R * FSTR)
#define SM_BYTES  ((TILE_R * FSTR + TILE_R) * 4)   // 52992

__global__ __launch_bounds__(192, 3) void fused_kernel(
    const float* __restrict__ self_v,   // [BN,128]
    const float* __restrict__ neigh,    // [BN,12,128]
    const float* __restrict__ nw,       // [BN,12]
    const float* __restrict__ extra,    // [BN,128]
    float* __restrict__ out)            // [BN,128]
{
    extern __shared__ uint32_t sm[];
    uint32_t* feat = sm;
    float* scores_s = (float*)(sm + SM_SCORES);
    uint32_t* cat_h = sm;               // aliases feat (dead after gemm1)

    const int tid = threadIdx.x, wid = tid >> 5, lane = tid & 31;
    const int g = lane >> 2, tg = lane & 3;
    const int bn0 = blockIdx.x * TILE_BN;
    const unsigned row0 = blockIdx.x * TILE_R;

    // ---- warp-local staging: warp stages ITS OWN rows 32*wid..32*wid+31.
    //      No CTA barrier needed before gemm1 (only __syncwarp).
    {
        const float4* ng4 = (const float4*)neigh;
        const float4* ex4 = (const float4*)extra;
        const int rbase = 32 * wid;
#pragma unroll 4
        for (int j = 0; j < 32; j++) {
            int r = rbase + j;
            unsigned gr = row0 + r;
            unsigned bnr = bn0 + r / KK;
            float4 nv = ng4[(size_t)gr * 32 + lane];
            float4 ev = __ldg(ex4 + (size_t)bnr * 32 + lane);
            *(uint2*)&feat[r * FSTR + 2 * lane] =
                make_uint2(packh(nv.x * ev.x, nv.y * ev.y),
                           packh(nv.z * ev.z, nv.w * ev.w));
        }
    }
    __syncwarp();

    // ---- gemm1: warp owns 2 m16 tiles, one at a time; nt unrolled x4
    const uint32_t fb = smem_u32(feat);
#pragma unroll
    for (int t = 0; t < 2; t++) {
        uint32_t A[8][4];
        {
            uint32_t ridx = (uint32_t)(32 * wid + 16 * t + (lane & 15));
#pragma unroll
            for (int kt = 0; kt < 8; kt++) {
                uint32_t idx = ridx * FSTR + kt * 8 + (lane >> 4) * 4;
                ldsm4(A[kt], fb + idx * 4);
            }
        }
        const unsigned gr = row0 + 32 * wid + 16 * t + g;
        const float nw0 = __ldg(nw + gr);
        const float nw1 = __ldg(nw + gr + 8);
        float rs0 = 0.f, rs1 = 0.f;

#pragma unroll
        for (int nt0 = 0; nt0 < 16; nt0 += 4) {
            float acc[4][4];
#pragma unroll
            for (int u = 0; u < 4; u++)
#pragma unroll
                for (int q = 0; q < 4; q++) acc[u][q] = 0.f;
#pragma unroll
            for (int kt = 0; kt < 8; kt++) {
#pragma unroll
                for (int u = 0; u < 4; u++) {
                    uint2 b = __ldg(&g_bfrag1[((nt0 + u) * 8 + kt) * 32 + lane]);
                    mma16816h(acc[u], A[kt][0], A[kt][1], A[kt][2], A[kt][3], b.x, b.y);
                }
            }
#pragma unroll
            for (int u = 0; u < 4; u++) {
                float4 ww = g_w1w2[(nt0 + u) * 4 + tg];
                float v0 = lrelu(acc[u][0] + nw0 * ww.x);
                float v1 = lrelu(acc[u][1] + nw0 * ww.y);
                float v2 = lrelu(acc[u][2] + nw1 * ww.x);
                float v3 = lrelu(acc[u][3] + nw1 * ww.y);
                rs0 = fmaf(v0, ww.z, fmaf(v1, ww.w, rs0));
                rs1 = fmaf(v2, ww.z, fmaf(v3, ww.w, rs1));
            }
        }
        rs0 += __shfl_xor_sync(0xffffffffu, rs0, 1);
        rs0 += __shfl_xor_sync(0xffffffffu, rs0, 2);
        rs1 += __shfl_xor_sync(0xffffffffu, rs1, 1);
        rs1 += __shfl_xor_sync(0xffffffffu, rs1, 2);
        if (tg == 0) {
            scores_s[32 * wid + 16 * t + g] = rs0;
            scores_s[32 * wid + 16 * t + g + 8] = rs1;
        }
    }
    __syncthreads();   // all feat reads done; scores visible; cat may overwrite feat

    // ---- softmax + agg + cat: 16 bn over 6 warps (agg reload = L2 hit)
    for (int bnl = wid; bnl < TILE_BN; bnl += NWARP) {
        const unsigned gbn = bn0 + bnl;
        float alpha[KK];
        {
            float s[KK];
#pragma unroll
            for (int k = 0; k < KK; k++) s[k] = scores_s[bnl * KK + k];
            float mx = s[0];
#pragma unroll
            for (int k = 1; k < KK; k++) mx = fmaxf(mx, s[k]);
            float tot = 0.f;
#pragma unroll
            for (int k = 0; k < KK; k++) { alpha[k] = __expf(s[k] - mx); tot += alpha[k]; }
            float inv = 1.f / tot;
#pragma unroll
            for (int k = 0; k < KK; k++) alpha[k] *= inv;
        }
        const float4* nb4 = (const float4*)neigh + (size_t)gbn * KK * 32;
        float4 agg = make_float4(0.f, 0.f, 0.f, 0.f);
#pragma unroll
        for (int k = 0; k < KK; k++) {
            float4 v = nb4[k * 32 + lane];
            agg.x = fmaf(alpha[k], v.x, agg.x);
            agg.y = fmaf(alpha[k], v.y, agg.y);
            agg.z = fmaf(alpha[k], v.z, agg.z);
            agg.w = fmaf(alpha[k], v.w, agg.w);
        }
        float4 sv = *((const float4*)self_v + (size_t)gbn * 32 + lane);
        cat_h[bnl * 132 + 2 * lane]          = packh(sv.x, sv.y);
        cat_h[bnl * 132 + 2 * lane + 1]      = packh(sv.z, sv.w);
        cat_h[bnl * 132 + 64 + 2 * lane]     = packh(agg.x, agg.y);
        cat_h[bnl * 132 + 64 + 2 * lane + 1] = packh(agg.z, agg.w);
    }
    __syncthreads();

    // ---- w3 GEMM: one full m16 tile (16 bn), 16 nt over 6 warps
    for (int nt = wid; nt < 16; nt += NWARP) {
        float acc3[4] = {0.f, 0.f, 0.f, 0.f};
#pragma unroll
        for (int kt = 0; kt < 16; kt++) {
            uint32_t a0 = cat_h[g * 132 + kt * 8 + tg];
            uint32_t a1 = cat_h[(g + 8) * 132 + kt * 8 + tg];
            uint32_t a2 = cat_h[g * 132 + kt * 8 + tg + 4];
            uint32_t a3 = cat_h[(g + 8) * 132 + kt * 8 + tg + 4];
            uint2 bq = __ldg(&g_bfrag3[(kt * 16 + nt) * 32 + lane]);
            mma16816h(acc3, a0, a1, a2, a3, bq.x, bq.y);
        }
        float2 o0 = make_float2(fmaxf(acc3[0], 0.f), fmaxf(acc3[1], 0.f));
        float2 o1 = make_float2(fmaxf(acc3[2], 0.f), fmaxf(acc3[3], 0.f));
        *(float2*)(out + (size_t)(bn0 + g) * DIMD + nt * 8 + 2 * tg) = o0;
        *(float2*)(out + (size_t)(bn0 + g + 8) * DIMD + nt * 8 + 2 * tg) = o1;
    }
}

// ---------------- launch ----------------
extern "C" void kernel_launch(void* const* d_in, const int* in_sizes, int n_in,
                              void* d_out, int out_size) {
    const float* self_v = (const float*)d_in[0];
    const float* neigh  = (const float*)d_in[1];
    const float* nw     = (const float*)d_in[2];
    const float* extra  = (const float*)d_in[3];
    const float* w1     = (const float*)d_in[6];
    const float* w2     = (const float*)d_in[7];
    const float* w3     = (const float*)d_in[8];
    float* out = (float*)d_out;

    static bool attr_set = false;
    if (!attr_set) {
        cudaFuncSetAttribute(fused_kernel, cudaFuncAttributeMaxDynamicSharedMemorySize, SM_BYTES);
        attr_set = true;
    }

    prep_kernel<<<49, 256>>>(w1, w2, w3);
    fused_kernel<<<GRID_F, 192, SM_BYTES>>>(self_v, neigh, nw, extra, out);
}